// round 9
// baseline (speedup 1.0000x reference)
#include <cuda_runtime.h>
#include <cuda_fp16.h>
#include <stdint.h>

#define B_    32
#define C_IN  128
#define H_    64
#define W_    64
#define K_    8
#define C_OUT 128
#define HID   512
#define HW    4096
#define NSTG  24            // k48 stages: 3 k16-chunks each, 72 chunks total

__device__ float g_pooled[B_ * C_IN];
__device__ float g_alphas[B_ * K_];
__device__ float g_aggb[B_ * C_OUT];
// x: [b][cb(8)][pixel(4096)][ci16] fp16 (1,048,576 B per b; 131,072 per cb)
__device__ __half g_xt[(size_t)B_ * HW * C_IN];
// w: [b][kk(72)][oc(128)][ci16] fp16 (294,912 B per b; 4096 B per kk=tap*8+cb)
__device__ __half g_aw[(size_t)B_ * 9 * C_OUT * C_IN];

__device__ __forceinline__ uint32_t smem_u32(const void* p) {
    uint32_t a;
    asm("{ .reg .u64 t; cvta.to.shared.u64 t, %1; cvt.u32.u64 %0, t; }" : "=r"(a) : "l"(p));
    return a;
}
#define CPA(dst, src, sz) \
    asm volatile("cp.async.cg.shared.global [%0], [%1], 16, %2;" :: "r"(dst), "l"(src), "r"(sz) : "memory")
#define CP_COMMIT() asm volatile("cp.async.commit_group;" ::: "memory")
#define CP_WAIT1()  asm volatile("cp.async.wait_group 1;" ::: "memory")
#define LDSM4(r, a) \
    asm volatile("ldmatrix.sync.aligned.m8n8.x4.shared.b16 {%0,%1,%2,%3}, [%4];" \
        : "=r"((r)[0]), "=r"((r)[1]), "=r"((r)[2]), "=r"((r)[3]) : "r"(a))
#define LDSM2(r, a) \
    asm volatile("ldmatrix.sync.aligned.m8n8.x2.shared.b16 {%0,%1}, [%2];" \
        : "=r"((r)[0]), "=r"((r)[1]) : "r"(a))
#define MMA(c, a, bb) \
    asm volatile("mma.sync.aligned.m16n8k16.row.col.f32.f16.f16.f32 " \
        "{%0,%1,%2,%3}, {%4,%5,%6,%7}, {%8,%9}, {%0,%1,%2,%3};" \
        : "+f"((c)[0]), "+f"((c)[1]), "+f"((c)[2]), "+f"((c)[3]) \
        : "r"((a)[0]), "r"((a)[1]), "r"((a)[2]), "r"((a)[3]), "r"((bb)[0]), "r"((bb)[1]))

// ---------- 1) pool ----------
__global__ __launch_bounds__(256) void pool_kernel(const float* __restrict__ x, float* __restrict__ pooled) {
    int bc = blockIdx.x;
    const float* p = x + (size_t)bc * HW;
    float s = 0.f;
    for (int i = threadIdx.x; i < HW; i += 256) s += p[i];
#pragma unroll
    for (int o = 16; o; o >>= 1) s += __shfl_xor_sync(~0u, s, o);
    __shared__ float red[8];
    if ((threadIdx.x & 31) == 0) red[threadIdx.x >> 5] = s;
    __syncthreads();
    if (threadIdx.x < 8) {
        s = red[threadIdx.x];
#pragma unroll
        for (int o = 4; o; o >>= 1) s += __shfl_xor_sync(0xffu, s, o);
        if (threadIdx.x == 0) pooled[bc] = s * (1.f / (float)HW);
    }
}

// ---------- 2) attention ----------
__global__ __launch_bounds__(512) void attn_kernel(const float* __restrict__ pooled, const float* __restrict__ prompt,
        const float* __restrict__ w1, const float* __restrict__ b1, const float* __restrict__ w2,
        const float* __restrict__ b2, const float* __restrict__ kbias,
        float* __restrict__ alphas, float* __restrict__ aggb) {
    int b = blockIdx.x, t = threadIdx.x;
    __shared__ float sp[C_IN], sh[HID], ss[HID], sc[K_], sal[K_];
    if (t < C_IN) sp[t] = pooled[b * C_IN + t];
    __syncthreads();
    { const float* wr = w1 + (size_t)t * C_IN; float a = b1[t];
#pragma unroll 8
      for (int i = 0; i < C_IN; i++) a = fmaf(sp[i], wr[i], a);
      sh[t] = fmaxf(a, 0.f); }
    __syncthreads();
    { const float* wr = w2 + (size_t)t * HID; float a = b2[t];
#pragma unroll 8
      for (int i = 0; i < HID; i++) a = fmaf(sh[i], wr[i], a);
      ss[t] = a; }
    __syncthreads();
    int wr = t >> 5, ln = t & 31;
    if (wr < K_) {
        const float* pr = prompt + (size_t)wr * HID;
        float a = 0.f;
        for (int i = ln; i < HID; i += 32) a = fmaf(ss[i], pr[i], a);
#pragma unroll
        for (int o = 16; o; o >>= 1) a += __shfl_xor_sync(~0u, a, o);
        if (ln == 0) sc[wr] = a;
    }
    __syncthreads();
    if (t == 0) {
        float m = sc[0];
#pragma unroll
        for (int k = 1; k < K_; k++) m = fmaxf(m, sc[k]);
        float e[K_], su = 0.f;
#pragma unroll
        for (int k = 0; k < K_; k++) { e[k] = __expf(sc[k] - m); su += e[k]; }
        float inv = 1.f / su;
#pragma unroll
        for (int k = 0; k < K_; k++) { sal[k] = e[k] * inv; alphas[b * K_ + k] = sal[k]; }
    }
    __syncthreads();
    if (t < C_OUT) {
        float a = 0.f;
#pragma unroll
        for (int k = 0; k < K_; k++) a = fmaf(sal[k], kbias[k * C_OUT + t], a);
        aggb[b * C_OUT + t] = a;
    }
}

// ---------- 3) weight agg -> [b][kk][oc][ci16] fp16 ----------
__global__ __launch_bounds__(128) void aggw_f16_kernel(const float* __restrict__ kw, const float* __restrict__ alphas,
        __half* __restrict__ A) {
    int oc = blockIdx.x, b = blockIdx.y, ci = threadIdx.x;
    __shared__ float skw[K_][C_IN * 9];
    __shared__ float a[K_];
    if (ci < K_) a[ci] = alphas[b * K_ + ci];
    for (int k = 0; k < K_; k++)
        for (int i = ci; i < C_IN * 9; i += 128)
            skw[k][i] = kw[(size_t)(k * C_OUT + oc) * (C_IN * 9) + i];
    __syncthreads();
    float acc[9];
#pragma unroll
    for (int t = 0; t < 9; t++) acc[t] = 0.f;
#pragma unroll
    for (int k = 0; k < K_; k++) {
        float al = a[k];
        const float* p = &skw[k][ci * 9];
#pragma unroll
        for (int t = 0; t < 9; t++) acc[t] = fmaf(al, p[t], acc[t]);
    }
#pragma unroll
    for (int t = 0; t < 9; t++) {
        size_t o = ((((size_t)(b * 9 + t) * 8 + (ci >> 4)) * C_OUT) + oc) * 16 + (ci & 15);
        A[o] = __float2half_rn(acc[t]);
    }
}

// ---------- 4) x -> [b][cb][p][ci16] fp16 ----------
__global__ __launch_bounds__(256) void xt_f16_kernel(const float* __restrict__ x, __half* __restrict__ X) {
    __shared__ float t[32][33];
    int b = blockIdx.z, p0 = blockIdx.x * 32, c0 = blockIdx.y * 32;
    int tx = threadIdx.x, ty = threadIdx.y;
    int tid = ty * 32 + tx;
#pragma unroll
    for (int i = 0; i < 4; i++)
        t[ty + 8 * i][tx] = x[((size_t)b * C_IN + c0 + ty + 8 * i) * HW + p0 + tx];
    __syncthreads();
#pragma unroll
    for (int i = 0; i < 2; i++) {
        int idx = tid + 256 * i;
        int sub  = idx & 7;
        int pxcb = idx >> 3;
        int pxl  = pxcb & 31;
        int cbl  = pxcb >> 5;
        int cl   = cbl * 16 + sub * 2;
        int c    = c0 + cl;
        __half2 v = __floats2half2_rn(t[cl][pxl], t[cl + 1][pxl]);
        size_t o = ((((size_t)b * 8 + (c >> 4)) * HW + p0 + pxl) * 16 + (c & 15)) >> 1;
        ((__half2*)X)[o] = v;
    }
}

// ---------- 5) HMMA conv: fp16 1-pass, R5 pipeline shape, k48 stages ----------
#define PITCH 48
#define CHUNK_SZ 18432u          // A 128x48 (6144) + B 256x48 (12288)
#define CHUNK_B  6144u
#define BUF_SZ  55296u           // 3 chunks
#define NBUF 3

__global__ __launch_bounds__(512, 1) void conv_mma_kernel(
        const __half* __restrict__ aw, const __half* __restrict__ xt,
        const float* __restrict__ aggb, float* __restrict__ out)
{
    extern __shared__ __align__(128) char sm[];
    const uint32_t sbase = smem_u32(sm);
    const int b  = blockIdx.x >> 4;
    const int y0 = (blockIdx.x & 15) * 4;
    const int tid = threadIdx.x, wid = tid >> 5, lane = tid & 31;
    const int warp_m = wid & 3, warp_n = wid >> 2;

    const int row  = tid >> 1, half = tid & 1;      // A: row=oc (tid<256); B: row=px
    const int py = row >> 6, pxx = row & 63;
    const uint32_t offA = (uint32_t)((warp_m * 32 + (lane & 15)) * PITCH + (lane >> 4) * 16);
    const uint32_t offB = (uint32_t)((warp_n * 64 + (lane & 7)) * PITCH + ((lane >> 3) & 1) * 16);

    float C[8][2][4];
#pragma unroll
    for (int i = 0; i < 8; i++)
#pragma unroll
        for (int j = 0; j < 2; j++)
#pragma unroll
            for (int q = 0; q < 4; q++) C[i][j][q] = 0.f;

#define ISSUE(s, buf) do { \
    uint32_t bs_ = (buf) * BUF_SZ; \
    _Pragma("unroll") \
    for (int c_ = 0; c_ < 3; c_++) { \
        int kk_ = 3 * (s) + c_; \
        int tap_ = kk_ >> 3, cb_ = kk_ & 7; \
        if (tid < 256) { \
            const char* as_ = (const char*)aw + (size_t)b * 294912 + (size_t)kk_ * 4096 + row * 32 + half * 16; \
            CPA(sbase + bs_ + c_ * CHUNK_SZ + row * PITCH + half * 16, as_, 16u); \
        } \
        int yy_ = y0 + py + tap_ / 3 - 1; \
        int xx_ = pxx + tap_ % 3 - 1; \
        bool v_ = ((unsigned)yy_ < 64u) && ((unsigned)xx_ < 64u); \
        size_t boff_ = (size_t)b * 1048576 + (size_t)cb_ * 131072 \
                     + (v_ ? (size_t)(yy_ * 64 + xx_) * 32 : 0) + half * 16; \
        CPA(sbase + bs_ + c_ * CHUNK_SZ + CHUNK_B + row * PITCH + half * 16, \
            (const char*)xt + boff_, v_ ? 16u : 0u); \
    } \
} while (0)

    ISSUE(0, 0); CP_COMMIT();
    ISSUE(1, 1); CP_COMMIT();

    int buf = 0;
    for (int s = 0; s < NSTG; s++) {
        CP_WAIT1();
        __syncthreads();
        if (s + 2 < NSTG) {
            int nb = buf + 2; if (nb >= NBUF) nb -= NBUF;
            ISSUE(s + 2, nb);
        }
        CP_COMMIT();

        const uint32_t bb = sbase + buf * BUF_SZ;
        if (++buf == NBUF) buf = 0;
#pragma unroll
        for (int c = 0; c < 3; c++) {
            const uint32_t ca = bb + c * CHUNK_SZ;
            uint32_t Af[2][4];
            LDSM4(Af[0], ca + offA);
            LDSM4(Af[1], ca + offA + 16 * PITCH);
#pragma unroll
            for (int ntp = 0; ntp < 4; ntp++) {
                uint32_t B0[2], B1[2];
                LDSM2(B0, ca + CHUNK_B + offB + (2 * ntp) * 8 * PITCH);
                LDSM2(B1, ca + CHUNK_B + offB + (2 * ntp + 1) * 8 * PITCH);
                MMA(C[2 * ntp][0], Af[0], B0);
                MMA(C[2 * ntp][1], Af[1], B0);
                MMA(C[2 * ntp + 1][0], Af[0], B1);
                MMA(C[2 * ntp + 1][1], Af[1], B1);
            }
        }
    }

    // --- epilogue: warp_n = row within 4-row block ---
    const int y = y0 + warp_n;
    float* orow = out + (size_t)b * 128 * HW + y * 64;
#pragma unroll
    for (int mt = 0; mt < 2; mt++) {
        int oc0 = warp_m * 32 + mt * 16 + (lane >> 2);
        float bi0 = aggb[b * 128 + oc0];
        float bi1 = aggb[b * 128 + oc0 + 8];
#pragma unroll
        for (int nt = 0; nt < 8; nt++) {
            int xcol = nt * 8 + 2 * (lane & 3);
            float2 v0 = { C[nt][mt][0] + bi0, C[nt][mt][1] + bi0 };
            float2 v1 = { C[nt][mt][2] + bi1, C[nt][mt][3] + bi1 };
            *(float2*)(orow + (size_t)oc0 * HW + xcol) = v0;
            *(float2*)(orow + (size_t)(oc0 + 8) * HW + xcol) = v1;
        }
    }
}

// ---------- host ----------
extern "C" void kernel_launch(void* const* d_in, const int* in_sizes, int n_in,
                              void* d_out, int out_size) {
    const float* x      = (const float*)d_in[0];
    const float* prompt = (const float*)d_in[1];
    const float* w1     = (const float*)d_in[2];
    const float* b1     = (const float*)d_in[3];
    const float* w2     = (const float*)d_in[4];
    const float* b2     = (const float*)d_in[5];
    const float* kw     = (const float*)d_in[6];
    const float* kbias  = (const float*)d_in[7];
    float* out = (float*)d_out;

    float *pooled, *alphas, *aggb;
    __half *xh, *awp;
    cudaGetSymbolAddress((void**)&pooled, g_pooled);
    cudaGetSymbolAddress((void**)&alphas, g_alphas);
    cudaGetSymbolAddress((void**)&aggb,   g_aggb);
    cudaGetSymbolAddress((void**)&xh,     g_xt);
    cudaGetSymbolAddress((void**)&awp,    g_aw);

    cudaFuncSetAttribute(conv_mma_kernel, cudaFuncAttributeMaxDynamicSharedMemorySize, NBUF * BUF_SZ);

    pool_kernel<<<B_ * C_IN, 256>>>(x, pooled);
    attn_kernel<<<B_, 512>>>(pooled, prompt, w1, b1, w2, b2, kbias, alphas, aggb);
    aggw_f16_kernel<<<dim3(C_OUT, B_), 128>>>(kw, alphas, awp);
    xt_f16_kernel<<<dim3(HW / 32, C_IN / 32, B_), dim3(32, 8)>>>(x, xh);
    conv_mma_kernel<<<512, 512, NBUF * BUF_SZ>>>(awp, xh, aggb, out);
}

// round 10
// speedup vs baseline: 1.1039x; 1.1039x over previous
#include <cuda_runtime.h>
#include <cuda_fp16.h>
#include <stdint.h>

#define B_    32
#define C_IN  128
#define H_    64
#define W_    64
#define K_    8
#define C_OUT 128
#define HID   512
#define HW    4096
#define NUNITS 1024         // unit = 2 rows (128 px)
#define GRID_P 296

__device__ float g_alphas[B_ * K_];
__device__ float g_aggb[B_ * C_OUT];
__device__ int   g_ctr;
// x: [b][cb(8)][pixel(4096)][ci16] fp16 (1,048,576 B per b)
__device__ __half g_xt[(size_t)B_ * HW * C_IN];
// w: [b][tap(9)][cb(8)][oc(128)][ci16] fp16 (294,912 B per b; 4096 B per stage)
__device__ __half g_aw[(size_t)B_ * 9 * C_OUT * C_IN];

__device__ __forceinline__ uint32_t smem_u32(const void* p) {
    uint32_t a;
    asm("{ .reg .u64 t; cvta.to.shared.u64 t, %1; cvt.u32.u64 %0, t; }" : "=r"(a) : "l"(p));
    return a;
}
#define CPA(dst, src, sz) \
    asm volatile("cp.async.cg.shared.global [%0], [%1], 16, %2;" :: "r"(dst), "l"(src), "r"(sz) : "memory")
#define CP_COMMIT() asm volatile("cp.async.commit_group;" ::: "memory")
#define CP_WAIT1()  asm volatile("cp.async.wait_group 1;" ::: "memory")
#define CP_WAIT2()  asm volatile("cp.async.wait_group 2;" ::: "memory")
#define LDSM4(r, a) \
    asm volatile("ldmatrix.sync.aligned.m8n8.x4.shared.b16 {%0,%1,%2,%3}, [%4];" \
        : "=r"((r)[0]), "=r"((r)[1]), "=r"((r)[2]), "=r"((r)[3]) : "r"(a))
#define LDSM2(r, a) \
    asm volatile("ldmatrix.sync.aligned.m8n8.x2.shared.b16 {%0,%1}, [%2];" \
        : "=r"((r)[0]), "=r"((r)[1]) : "r"(a))
#define MMA(c, a, bb) \
    asm volatile("mma.sync.aligned.m16n8k16.row.col.f32.f16.f16.f32 " \
        "{%0,%1,%2,%3}, {%4,%5,%6,%7}, {%8,%9}, {%0,%1,%2,%3};" \
        : "+f"((c)[0]), "+f"((c)[1]), "+f"((c)[2]), "+f"((c)[3]) \
        : "r"((a)[0]), "r"((a)[1]), "r"((a)[2]), "r"((a)[3]), "r"((bb)[0]), "r"((bb)[1]))

// ---------- 1) x -> [b][cb][p][ci16] fp16 ----------
__global__ __launch_bounds__(256) void xt_f16_kernel(const float* __restrict__ x, __half* __restrict__ X) {
    __shared__ float t[32][33];
    int b = blockIdx.z, p0 = blockIdx.x * 32, c0 = blockIdx.y * 32;
    int tx = threadIdx.x, ty = threadIdx.y;
    int tid = ty * 32 + tx;
#pragma unroll
    for (int i = 0; i < 4; i++)
        t[ty + 8 * i][tx] = x[((size_t)b * C_IN + c0 + ty + 8 * i) * HW + p0 + tx];
    __syncthreads();
#pragma unroll
    for (int i = 0; i < 2; i++) {
        int idx = tid + 256 * i;
        int sub  = idx & 7;
        int pxcb = idx >> 3;
        int pxl  = pxcb & 31;
        int cbl  = pxcb >> 5;
        int cl   = cbl * 16 + sub * 2;
        int c    = c0 + cl;
        __half2 v = __floats2half2_rn(t[cl][pxl], t[cl + 1][pxl]);
        size_t o = ((((size_t)b * 8 + (c >> 4)) * HW + p0 + pxl) * 16 + (c & 15)) >> 1;
        ((__half2*)X)[o] = v;
    }
}

// ---------- 2) fused pool + attention ----------
__global__ __launch_bounds__(512) void poolattn_kernel(const float* __restrict__ x,
        const float* __restrict__ prompt,
        const float* __restrict__ w1, const float* __restrict__ b1, const float* __restrict__ w2,
        const float* __restrict__ b2, const float* __restrict__ kbias,
        float* __restrict__ alphas, float* __restrict__ aggb) {
    int b = blockIdx.x, t = threadIdx.x;
    int wr = t >> 5, ln = t & 31;
    __shared__ float sp[C_IN], sh[HID], ss[HID], sc[K_], sal[K_];

    // pool: warp wr handles channels wr*8 .. wr*8+7
#pragma unroll
    for (int j = 0; j < 8; j++) {
        int c = wr * 8 + j;
        const float4* p4 = (const float4*)(x + ((size_t)b * C_IN + c) * HW);
        float s = 0.f;
        for (int i = ln; i < HW / 4; i += 32) {
            float4 v = p4[i];
            s += v.x + v.y + v.z + v.w;
        }
#pragma unroll
        for (int o = 16; o; o >>= 1) s += __shfl_xor_sync(~0u, s, o);
        if (ln == 0) sp[c] = s * (1.f / (float)HW);
    }
    __syncthreads();

    { const float* wrow = w1 + (size_t)t * C_IN; float a = b1[t];
#pragma unroll 8
      for (int i = 0; i < C_IN; i++) a = fmaf(sp[i], wrow[i], a);
      sh[t] = fmaxf(a, 0.f); }
    __syncthreads();
    { const float* wrow = w2 + (size_t)t * HID; float a = b2[t];
#pragma unroll 8
      for (int i = 0; i < HID; i++) a = fmaf(sh[i], wrow[i], a);
      ss[t] = a; }
    __syncthreads();
    if (wr < K_) {
        const float* pr = prompt + (size_t)wr * HID;
        float a = 0.f;
        for (int i = ln; i < HID; i += 32) a = fmaf(ss[i], pr[i], a);
#pragma unroll
        for (int o = 16; o; o >>= 1) a += __shfl_xor_sync(~0u, a, o);
        if (ln == 0) sc[wr] = a;
    }
    __syncthreads();
    if (t == 0) {
        float m = sc[0];
#pragma unroll
        for (int k = 1; k < K_; k++) m = fmaxf(m, sc[k]);
        float e[K_], su = 0.f;
#pragma unroll
        for (int k = 0; k < K_; k++) { e[k] = __expf(sc[k] - m); su += e[k]; }
        float inv = 1.f / su;
#pragma unroll
        for (int k = 0; k < K_; k++) { sal[k] = e[k] * inv; alphas[b * K_ + k] = sal[k]; }
    }
    __syncthreads();
    if (t < C_OUT) {
        float a = 0.f;
#pragma unroll
        for (int k = 0; k < K_; k++) a = fmaf(sal[k], kbias[k * C_OUT + t], a);
        aggb[b * C_OUT + t] = a;
    }
}

// ---------- 3) weight agg -> [b][tap][cb][oc][ci16] fp16 (+ counter reset) ----------
__global__ __launch_bounds__(128) void aggw_f16_kernel(const float* __restrict__ kw, const float* __restrict__ alphas,
        __half* __restrict__ A) {
    if (blockIdx.x == 0 && blockIdx.y == 0 && threadIdx.x == 0) g_ctr = 0;
    int oc = blockIdx.x, b = blockIdx.y, ci = threadIdx.x;
    __shared__ float skw[K_][C_IN * 9];
    __shared__ float a[K_];
    if (ci < K_) a[ci] = alphas[b * K_ + ci];
    for (int k = 0; k < K_; k++)
        for (int i = ci; i < C_IN * 9; i += 128)
            skw[k][i] = kw[(size_t)(k * C_OUT + oc) * (C_IN * 9) + i];
    __syncthreads();
    float acc[9];
#pragma unroll
    for (int t = 0; t < 9; t++) acc[t] = 0.f;
#pragma unroll
    for (int k = 0; k < K_; k++) {
        float al = a[k];
        const float* p = &skw[k][ci * 9];
#pragma unroll
        for (int t = 0; t < 9; t++) acc[t] = fmaf(al, p[t], acc[t]);
    }
#pragma unroll
    for (int t = 0; t < 9; t++) {
        size_t o = ((((size_t)(b * 9 + t) * 8 + (ci >> 4)) * C_OUT) + oc) * 16 + (ci & 15);
        A[o] = __float2half_rn(acc[t]);
    }
}

// ---------- 4) persistent HMMA conv: fragment double-buffered ----------
#define PITCH 48
#define SM_A  0
#define SM_B  6144
#define BUF_SZ 12288
__global__ __launch_bounds__(256, 2) void conv_mma_kernel(
        const __half* __restrict__ aw, const __half* __restrict__ xt,
        const float* __restrict__ aggb, float* __restrict__ out)
{
    extern __shared__ __align__(128) char sm[];
    const uint32_t sbase = smem_u32(sm);
    __shared__ int s_nu[2];
    const int tid = threadIdx.x, wid = tid >> 5, lane = tid & 31;
    const int warp_m = wid & 3, warp_n = wid >> 2;

    const int row  = tid >> 1, half = tid & 1;
    const uint32_t aDst = sbase + SM_A + row * PITCH + half * 16;
    const uint32_t bDst = sbase + SM_B + row * PITCH + half * 16;
    const uint32_t offA = (uint32_t)((warp_m * 32 + (lane & 15)) * PITCH + (lane >> 4) * 16);
    const uint32_t offB = (uint32_t)((warp_n * 64 + (lane & 7)) * PITCH + ((lane >> 3) & 1) * 16);

    if (tid == 0) s_nu[0] = atomicAdd(&g_ctr, 1);
    __syncthreads();
    int c_u = s_nu[0];
    if (tid == 0) s_nu[1] = atomicAdd(&g_ctr, 1);
    int nslot = 1;

    int l_u = c_u, l_s = 0, l_buf = 0;

    float C[8][2][4];
#pragma unroll
    for (int i = 0; i < 8; i++)
#pragma unroll
        for (int j = 0; j < 2; j++)
#pragma unroll
            for (int q = 0; q < 4; q++) C[i][j][q] = 0.f;

#define ISSUE() do { \
    if (l_u < NUNITS) { \
        int b_ = l_u >> 5, y0_ = (l_u & 31) * 2; \
        int tap_ = l_s >> 3, cb_ = l_s & 7; \
        int yy_ = y0_ + (row >> 6) + tap_ / 3 - 1; \
        int xx_ = (row & 63) + tap_ % 3 - 1; \
        bool v_ = ((unsigned)yy_ < 64u) && ((unsigned)xx_ < 64u); \
        size_t boff_ = (size_t)b_ * 1048576 + (size_t)cb_ * 131072 \
                     + (v_ ? (size_t)(yy_ * 64 + xx_) * 32 : 0) + half * 16; \
        unsigned bsz_ = v_ ? 16u : 0u; \
        uint32_t bs_ = l_buf * BUF_SZ; \
        CPA(aDst + bs_, (const char*)aw + (size_t)b_ * 294912 + l_s * 4096 + row * 32 + half * 16, 16u); \
        CPA(bDst + bs_, (const char*)xt + boff_, bsz_); \
    } \
    l_s++; l_buf = (l_buf + 1) & 3; \
} while (0)

    ISSUE(); CP_COMMIT();
    ISSUE(); CP_COMMIT();
    ISSUE(); CP_COMMIT();

    uint32_t fA0[2][4], fB0[8][2], fA1[2][4], fB1[8][2];

    // prologue: fragments for chunk 0 (buffer 0 complete after wait_group 2)
    CP_WAIT2();
    __syncthreads();
    {
        const uint32_t bb = sbase;
        LDSM4(fA0[0], bb + SM_A + offA);
        LDSM4(fA0[1], bb + SM_A + offA + 16 * PITCH);
#pragma unroll
        for (int nt = 0; nt < 8; nt++) LDSM2(fB0[nt], bb + SM_B + offB + nt * 8 * PITCH);
    }
    int c_buf = 1;   // buffer holding the NEXT chunk's data

#define STEP(CA, CB, NA, NB) do { \
    CP_WAIT1(); \
    __syncthreads(); \
    if (l_s == 72) { l_u = s_nu[nslot]; l_s = 0; } \
    ISSUE(); \
    CP_COMMIT(); \
    const uint32_t bbN = sbase + c_buf * BUF_SZ; \
    c_buf = (c_buf + 1) & 3; \
    LDSM4(NA[0], bbN + SM_A + offA); \
    LDSM4(NA[1], bbN + SM_A + offA + 16 * PITCH); \
    _Pragma("unroll") \
    for (int nt = 0; nt < 8; nt++) LDSM2(NB[nt], bbN + SM_B + offB + nt * 8 * PITCH); \
    _Pragma("unroll") \
    for (int nt = 0; nt < 8; nt++) { \
        MMA(C[nt][0], CA[0], CB[nt]); \
        MMA(C[nt][1], CA[1], CB[nt]); \
    } \
} while (0)

    while (c_u < NUNITS) {
        for (int c_s = 0; c_s < 72; c_s += 2) {
            STEP(fA0, fB0, fA1, fB1);
            STEP(fA1, fB1, fA0, fB0);
        }

        // epilogue for unit c_u (cur=fA0/fB0 now holds next unit's chunk 0)
        {
            int b_ = c_u >> 5, y_ = (c_u & 31) * 2 + warp_n;
            float* orow = out + (size_t)b_ * 128 * HW + y_ * 64;
#pragma unroll
            for (int mt = 0; mt < 2; mt++) {
                int oc0 = warp_m * 32 + mt * 16 + (lane >> 2);
                float bi0 = aggb[b_ * 128 + oc0];
                float bi1 = aggb[b_ * 128 + oc0 + 8];
#pragma unroll
                for (int nt = 0; nt < 8; nt++) {
                    int xcol = nt * 8 + 2 * (lane & 3);
                    float2 w0 = { C[nt][mt][0] + bi0, C[nt][mt][1] + bi0 };
                    float2 w1 = { C[nt][mt][2] + bi1, C[nt][mt][3] + bi1 };
                    *(float2*)(orow + (size_t)oc0 * HW + xcol) = w0;
                    *(float2*)(orow + (size_t)(oc0 + 8) * HW + xcol) = w1;
                }
            }
        }
#pragma unroll
        for (int i = 0; i < 8; i++)
#pragma unroll
            for (int j = 0; j < 2; j++)
#pragma unroll
                for (int q = 0; q < 4; q++) C[i][j][q] = 0.f;

        c_u = s_nu[nslot];
        nslot ^= 1;
        if (tid == 0) s_nu[nslot] = atomicAdd(&g_ctr, 1);
    }
}

// ---------- host ----------
extern "C" void kernel_launch(void* const* d_in, const int* in_sizes, int n_in,
                              void* d_out, int out_size) {
    const float* x      = (const float*)d_in[0];
    const float* prompt = (const float*)d_in[1];
    const float* w1     = (const float*)d_in[2];
    const float* b1     = (const float*)d_in[3];
    const float* w2     = (const float*)d_in[4];
    const float* b2     = (const float*)d_in[5];
    const float* kw     = (const float*)d_in[6];
    const float* kbias  = (const float*)d_in[7];
    float* out = (float*)d_out;

    float *alphas, *aggb;
    __half *xh, *awp;
    cudaGetSymbolAddress((void**)&alphas, g_alphas);
    cudaGetSymbolAddress((void**)&aggb,   g_aggb);
    cudaGetSymbolAddress((void**)&xh,     g_xt);
    cudaGetSymbolAddress((void**)&awp,    g_aw);

    cudaFuncSetAttribute(conv_mma_kernel, cudaFuncAttributeMaxDynamicSharedMemorySize, 4 * BUF_SZ);

    xt_f16_kernel<<<dim3(HW / 32, C_IN / 32, B_), dim3(32, 8)>>>(x, xh);
    poolattn_kernel<<<B_, 512>>>(x, prompt, w1, b1, w2, b2, kbias, alphas, aggb);
    aggw_f16_kernel<<<dim3(C_OUT, B_), 128>>>(kw, alphas, awp);
    conv_mma_kernel<<<GRID_P, 256, 4 * BUF_SZ>>>(awp, xh, aggb, out);
}

// round 11
// speedup vs baseline: 1.6843x; 1.5257x over previous
#include <cuda_runtime.h>
#include <cuda_fp16.h>
#include <stdint.h>

#define B_    32
#define C_IN  128
#define H_    64
#define W_    64
#define K_    8
#define C_OUT 128
#define HID   512
#define HW    4096
#define NUNITS 1024         // unit = 2 rows (128 px)
#define GRID_P 296

__device__ float g_alphas[B_ * K_];
__device__ float g_aggb[B_ * C_OUT];
__device__ int   g_ctr;
// x: [b][cb(8)][pixel(4096)][ci16] fp16 (1,048,576 B per b)
__device__ __half g_xt[(size_t)B_ * HW * C_IN];
// w: [b][tap(9)][cb(8)][oc(128)][ci16] fp16 (294,912 B per b; 4096 B per stage)
__device__ __half g_aw[(size_t)B_ * 9 * C_OUT * C_IN];

__device__ __forceinline__ uint32_t smem_u32(const void* p) {
    uint32_t a;
    asm("{ .reg .u64 t; cvta.to.shared.u64 t, %1; cvt.u32.u64 %0, t; }" : "=r"(a) : "l"(p));
    return a;
}
#define CPA(dst, src, sz) \
    asm volatile("cp.async.cg.shared.global [%0], [%1], 16, %2;" :: "r"(dst), "l"(src), "r"(sz) : "memory")
#define CP_COMMIT() asm volatile("cp.async.commit_group;" ::: "memory")
#define CP_WAIT1()  asm volatile("cp.async.wait_group 1;" ::: "memory")
#define CP_WAIT2()  asm volatile("cp.async.wait_group 2;" ::: "memory")
#define LDSM4(r, a) \
    asm volatile("ldmatrix.sync.aligned.m8n8.x4.shared.b16 {%0,%1,%2,%3}, [%4];" \
        : "=r"((r)[0]), "=r"((r)[1]), "=r"((r)[2]), "=r"((r)[3]) : "r"(a))
#define LDSM2(r, a) \
    asm volatile("ldmatrix.sync.aligned.m8n8.x2.shared.b16 {%0,%1}, [%2];" \
        : "=r"((r)[0]), "=r"((r)[1]) : "r"(a))
#define MMA(c, a, bb) \
    asm volatile("mma.sync.aligned.m16n8k16.row.col.f32.f16.f16.f32 " \
        "{%0,%1,%2,%3}, {%4,%5,%6,%7}, {%8,%9}, {%0,%1,%2,%3};" \
        : "+f"((c)[0]), "+f"((c)[1]), "+f"((c)[2]), "+f"((c)[3]) \
        : "r"((a)[0]), "r"((a)[1]), "r"((a)[2]), "r"((a)[3]), "r"((bb)[0]), "r"((bb)[1]))

// ---------- 1) x -> [b][cb][p][ci16] fp16 ----------
__global__ __launch_bounds__(256) void xt_f16_kernel(const float* __restrict__ x, __half* __restrict__ X) {
    __shared__ float t[32][33];
    int b = blockIdx.z, p0 = blockIdx.x * 32, c0 = blockIdx.y * 32;
    int tx = threadIdx.x, ty = threadIdx.y;
    int tid = ty * 32 + tx;
#pragma unroll
    for (int i = 0; i < 4; i++)
        t[ty + 8 * i][tx] = x[((size_t)b * C_IN + c0 + ty + 8 * i) * HW + p0 + tx];
    __syncthreads();
#pragma unroll
    for (int i = 0; i < 2; i++) {
        int idx = tid + 256 * i;
        int sub  = idx & 7;
        int pxcb = idx >> 3;
        int pxl  = pxcb & 31;
        int cbl  = pxcb >> 5;
        int cl   = cbl * 16 + sub * 2;
        int c    = c0 + cl;
        __half2 v = __floats2half2_rn(t[cl][pxl], t[cl + 1][pxl]);
        size_t o = ((((size_t)b * 8 + (c >> 4)) * HW + p0 + pxl) * 16 + (c & 15)) >> 1;
        ((__half2*)X)[o] = v;
    }
}

// ---------- 2) fused pool + attention (coalesced MLP) ----------
__global__ __launch_bounds__(512) void poolattn_kernel(const float* __restrict__ x,
        const float* __restrict__ prompt,
        const float* __restrict__ w1, const float* __restrict__ b1, const float* __restrict__ w2,
        const float* __restrict__ b2, const float* __restrict__ kbias,
        float* __restrict__ alphas, float* __restrict__ aggb) {
    int b = blockIdx.x, t = threadIdx.x;
    int wr = t >> 5, ln = t & 31;
    __shared__ float sp[C_IN], sh[HID], ss[HID], sc[K_], sal[K_];

    // pool: warp wr handles channels wr*8 .. wr*8+7 (coalesced float4)
#pragma unroll
    for (int j = 0; j < 8; j++) {
        int c = wr * 8 + j;
        const float4* p4 = (const float4*)(x + ((size_t)b * C_IN + c) * HW);
        float s = 0.f;
        for (int i = ln; i < HW / 4; i += 32) {
            float4 v = p4[i];
            s += v.x + v.y + v.z + v.w;
        }
#pragma unroll
        for (int o = 16; o; o >>= 1) s += __shfl_xor_sync(~0u, s, o);
        if (ln == 0) sp[c] = s * (1.f / (float)HW);
    }
    __syncthreads();

    // h = relu(W1 @ pooled + b1): warp computes 32 outputs, lanes split the row
    {
        const float4* sp4 = (const float4*)sp;
        float4 pv = sp4[ln];                      // lane's quarter... (128 floats = 32 float4)
#pragma unroll 4
        for (int jj = 0; jj < 32; jj++) {
            int j = wr * 32 + jj;
            float4 wv = ((const float4*)(w1 + (size_t)j * C_IN))[ln];
            float a = wv.x * pv.x + wv.y * pv.y + wv.z * pv.z + wv.w * pv.w;
#pragma unroll
            for (int o = 16; o; o >>= 1) a += __shfl_xor_sync(~0u, a, o);
            if (ln == 0) sh[j] = fmaxf(a + b1[j], 0.f);
        }
    }
    __syncthreads();

    // s = W2 @ h + b2: warp computes 32 outputs, lanes split 512-row (4 float4 each)
    {
        const float4* sh4 = (const float4*)sh;
        float4 hv[4];
#pragma unroll
        for (int q = 0; q < 4; q++) hv[q] = sh4[ln + 32 * q];
#pragma unroll 2
        for (int jj = 0; jj < 32; jj++) {
            int j = wr * 32 + jj;
            const float4* row = (const float4*)(w2 + (size_t)j * HID);
            float a = 0.f;
#pragma unroll
            for (int q = 0; q < 4; q++) {
                float4 wv = row[ln + 32 * q];
                a = fmaf(wv.x, hv[q].x, a);
                a = fmaf(wv.y, hv[q].y, a);
                a = fmaf(wv.z, hv[q].z, a);
                a = fmaf(wv.w, hv[q].w, a);
            }
#pragma unroll
            for (int o = 16; o; o >>= 1) a += __shfl_xor_sync(~0u, a, o);
            if (ln == 0) ss[j] = a + b2[j];
        }
    }
    __syncthreads();

    if (wr < K_) {
        const float* pr = prompt + (size_t)wr * HID;
        float a = 0.f;
        for (int i = ln; i < HID; i += 32) a = fmaf(ss[i], pr[i], a);
#pragma unroll
        for (int o = 16; o; o >>= 1) a += __shfl_xor_sync(~0u, a, o);
        if (ln == 0) sc[wr] = a;
    }
    __syncthreads();
    if (t == 0) {
        float m = sc[0];
#pragma unroll
        for (int k = 1; k < K_; k++) m = fmaxf(m, sc[k]);
        float e[K_], su = 0.f;
#pragma unroll
        for (int k = 0; k < K_; k++) { e[k] = __expf(sc[k] - m); su += e[k]; }
        float inv = 1.f / su;
#pragma unroll
        for (int k = 0; k < K_; k++) { sal[k] = e[k] * inv; alphas[b * K_ + k] = sal[k]; }
    }
    __syncthreads();
    if (t < C_OUT) {
        float a = 0.f;
#pragma unroll
        for (int k = 0; k < K_; k++) a = fmaf(sal[k], kbias[k * C_OUT + t], a);
        aggb[b * C_OUT + t] = a;
    }
}

// ---------- 3) weight agg -> [b][tap][cb][oc][ci16] fp16 (+ counter reset) ----------
__global__ __launch_bounds__(128) void aggw_f16_kernel(const float* __restrict__ kw, const float* __restrict__ alphas,
        __half* __restrict__ A) {
    if (blockIdx.x == 0 && blockIdx.y == 0 && threadIdx.x == 0) g_ctr = 0;
    int oc = blockIdx.x, b = blockIdx.y, ci = threadIdx.x;
    __shared__ float skw[K_][C_IN * 9];
    __shared__ float a[K_];
    if (ci < K_) a[ci] = alphas[b * K_ + ci];
    for (int k = 0; k < K_; k++)
        for (int i = ci; i < C_IN * 9; i += 128)
            skw[k][i] = kw[(size_t)(k * C_OUT + oc) * (C_IN * 9) + i];
    __syncthreads();
    float acc[9];
#pragma unroll
    for (int t = 0; t < 9; t++) acc[t] = 0.f;
#pragma unroll
    for (int k = 0; k < K_; k++) {
        float al = a[k];
        const float* p = &skw[k][ci * 9];
#pragma unroll
        for (int t = 0; t < 9; t++) acc[t] = fmaf(al, p[t], acc[t]);
    }
#pragma unroll
    for (int t = 0; t < 9; t++) {
        size_t o = ((((size_t)(b * 9 + t) * 8 + (ci >> 4)) * C_OUT) + oc) * 16 + (ci & 15);
        A[o] = __float2half_rn(acc[t]);
    }
}

// ---------- 4) persistent HMMA conv: fragment double-buffered (R10) ----------
#define PITCH 48
#define SM_A  0
#define SM_B  6144
#define BUF_SZ 12288
__global__ __launch_bounds__(256, 2) void conv_mma_kernel(
        const __half* __restrict__ aw, const __half* __restrict__ xt,
        const float* __restrict__ aggb, float* __restrict__ out)
{
    extern __shared__ __align__(128) char sm[];
    const uint32_t sbase = smem_u32(sm);
    __shared__ int s_nu[2];
    const int tid = threadIdx.x, wid = tid >> 5, lane = tid & 31;
    const int warp_m = wid & 3, warp_n = wid >> 2;

    const int row  = tid >> 1, half = tid & 1;
    const uint32_t aDst = sbase + SM_A + row * PITCH + half * 16;
    const uint32_t bDst = sbase + SM_B + row * PITCH + half * 16;
    const uint32_t offA = (uint32_t)((warp_m * 32 + (lane & 15)) * PITCH + (lane >> 4) * 16);
    const uint32_t offB = (uint32_t)((warp_n * 64 + (lane & 7)) * PITCH + ((lane >> 3) & 1) * 16);

    if (tid == 0) s_nu[0] = atomicAdd(&g_ctr, 1);
    __syncthreads();
    int c_u = s_nu[0];
    if (tid == 0) s_nu[1] = atomicAdd(&g_ctr, 1);
    int nslot = 1;

    int l_u = c_u, l_s = 0, l_buf = 0;

    float C[8][2][4];
#pragma unroll
    for (int i = 0; i < 8; i++)
#pragma unroll
        for (int j = 0; j < 2; j++)
#pragma unroll
            for (int q = 0; q < 4; q++) C[i][j][q] = 0.f;

#define ISSUE() do { \
    if (l_u < NUNITS) { \
        int b_ = l_u >> 5, y0_ = (l_u & 31) * 2; \
        int tap_ = l_s >> 3, cb_ = l_s & 7; \
        int yy_ = y0_ + (row >> 6) + tap_ / 3 - 1; \
        int xx_ = (row & 63) + tap_ % 3 - 1; \
        bool v_ = ((unsigned)yy_ < 64u) && ((unsigned)xx_ < 64u); \
        size_t boff_ = (size_t)b_ * 1048576 + (size_t)cb_ * 131072 \
                     + (v_ ? (size_t)(yy_ * 64 + xx_) * 32 : 0) + half * 16; \
        unsigned bsz_ = v_ ? 16u : 0u; \
        uint32_t bs_ = l_buf * BUF_SZ; \
        CPA(aDst + bs_, (const char*)aw + (size_t)b_ * 294912 + l_s * 4096 + row * 32 + half * 16, 16u); \
        CPA(bDst + bs_, (const char*)xt + boff_, bsz_); \
    } \
    l_s++; l_buf = (l_buf + 1) & 3; \
} while (0)

    ISSUE(); CP_COMMIT();
    ISSUE(); CP_COMMIT();
    ISSUE(); CP_COMMIT();

    uint32_t fA0[2][4], fB0[8][2], fA1[2][4], fB1[8][2];

    CP_WAIT2();
    __syncthreads();
    {
        const uint32_t bb = sbase;
        LDSM4(fA0[0], bb + SM_A + offA);
        LDSM4(fA0[1], bb + SM_A + offA + 16 * PITCH);
#pragma unroll
        for (int nt = 0; nt < 8; nt++) LDSM2(fB0[nt], bb + SM_B + offB + nt * 8 * PITCH);
    }
    int c_buf = 1;

#define STEP(CA, CB, NA, NB) do { \
    CP_WAIT1(); \
    __syncthreads(); \
    if (l_s == 72) { l_u = s_nu[nslot]; l_s = 0; } \
    ISSUE(); \
    CP_COMMIT(); \
    const uint32_t bbN = sbase + c_buf * BUF_SZ; \
    c_buf = (c_buf + 1) & 3; \
    LDSM4(NA[0], bbN + SM_A + offA); \
    LDSM4(NA[1], bbN + SM_A + offA + 16 * PITCH); \
    _Pragma("unroll") \
    for (int nt = 0; nt < 8; nt++) LDSM2(NB[nt], bbN + SM_B + offB + nt * 8 * PITCH); \
    _Pragma("unroll") \
    for (int nt = 0; nt < 8; nt++) { \
        MMA(C[nt][0], CA[0], CB[nt]); \
        MMA(C[nt][1], CA[1], CB[nt]); \
    } \
} while (0)

    while (c_u < NUNITS) {
        for (int c_s = 0; c_s < 72; c_s += 2) {
            STEP(fA0, fB0, fA1, fB1);
            STEP(fA1, fB1, fA0, fB0);
        }
        {
            int b_ = c_u >> 5, y_ = (c_u & 31) * 2 + warp_n;
            float* orow = out + (size_t)b_ * 128 * HW + y_ * 64;
#pragma unroll
            for (int mt = 0; mt < 2; mt++) {
                int oc0 = warp_m * 32 + mt * 16 + (lane >> 2);
                float bi0 = aggb[b_ * 128 + oc0];
                float bi1 = aggb[b_ * 128 + oc0 + 8];
#pragma unroll
                for (int nt = 0; nt < 8; nt++) {
                    int xcol = nt * 8 + 2 * (lane & 3);
                    float2 w0 = { C[nt][mt][0] + bi0, C[nt][mt][1] + bi0 };
                    float2 w1v = { C[nt][mt][2] + bi1, C[nt][mt][3] + bi1 };
                    *(float2*)(orow + (size_t)oc0 * HW + xcol) = w0;
                    *(float2*)(orow + (size_t)(oc0 + 8) * HW + xcol) = w1v;
                }
            }
        }
#pragma unroll
        for (int i = 0; i < 8; i++)
#pragma unroll
            for (int j = 0; j < 2; j++)
#pragma unroll
                for (int q = 0; q < 4; q++) C[i][j][q] = 0.f;

        c_u = s_nu[nslot];
        nslot ^= 1;
        if (tid == 0) s_nu[nslot] = atomicAdd(&g_ctr, 1);
    }
}

// ---------- host ----------
extern "C" void kernel_launch(void* const* d_in, const int* in_sizes, int n_in,
                              void* d_out, int out_size) {
    const float* x      = (const float*)d_in[0];
    const float* prompt = (const float*)d_in[1];
    const float* w1     = (const float*)d_in[2];
    const float* b1     = (const float*)d_in[3];
    const float* w2     = (const float*)d_in[4];
    const float* b2     = (const float*)d_in[5];
    const float* kw     = (const float*)d_in[6];
    const float* kbias  = (const float*)d_in[7];
    float* out = (float*)d_out;

    float *alphas, *aggb;
    __half *xh, *awp;
    cudaGetSymbolAddress((void**)&alphas, g_alphas);
    cudaGetSymbolAddress((void**)&aggb,   g_aggb);
    cudaGetSymbolAddress((void**)&xh,     g_xt);
    cudaGetSymbolAddress((void**)&awp,    g_aw);

    cudaFuncSetAttribute(conv_mma_kernel, cudaFuncAttributeMaxDynamicSharedMemorySize, 4 * BUF_SZ);

    xt_f16_kernel<<<dim3(HW / 32, C_IN / 32, B_), dim3(32, 8)>>>(x, xh);
    poolattn_kernel<<<B_, 512>>>(x, prompt, w1, b1, w2, b2, kbias, alphas, aggb);
    aggw_f16_kernel<<<dim3(C_OUT, B_), 128>>>(kw, alphas, awp);
    conv_mma_kernel<<<GRID_P, 256, 4 * BUF_SZ>>>(awp, xh, aggb, out);
}

// round 12
// speedup vs baseline: 1.8695x; 1.1099x over previous
#include <cuda_runtime.h>
#include <cuda_fp16.h>
#include <stdint.h>

#define B_    32
#define C_IN  128
#define H_    64
#define W_    64
#define K_    8
#define C_OUT 128
#define HID   512
#define HW    4096
#define NUNITS 1024
#define GRID_P 296

__device__ float g_ppart[(size_t)B_ * C_IN * 128];   // [b][c][pblk] partial sums
__device__ float g_alphas[B_ * K_];
__device__ float g_aggb[B_ * C_OUT];
__device__ int   g_ctr;
__device__ __half g_xt[(size_t)B_ * HW * C_IN];      // [b][cb][p][ci16]
__device__ __half g_aw[(size_t)B_ * 9 * C_OUT * C_IN]; // [b][tap][cb][oc][ci16]

__device__ __forceinline__ uint32_t smem_u32(const void* p) {
    uint32_t a;
    asm("{ .reg .u64 t; cvta.to.shared.u64 t, %1; cvt.u32.u64 %0, t; }" : "=r"(a) : "l"(p));
    return a;
}
#define CPA(dst, src, sz) \
    asm volatile("cp.async.cg.shared.global [%0], [%1], 16, %2;" :: "r"(dst), "l"(src), "r"(sz) : "memory")
#define CP_COMMIT() asm volatile("cp.async.commit_group;" ::: "memory")
#define CP_WAIT1()  asm volatile("cp.async.wait_group 1;" ::: "memory")
#define CP_WAIT2()  asm volatile("cp.async.wait_group 2;" ::: "memory")
#define LDSM4(r, a) \
    asm volatile("ldmatrix.sync.aligned.m8n8.x4.shared.b16 {%0,%1,%2,%3}, [%4];" \
        : "=r"((r)[0]), "=r"((r)[1]), "=r"((r)[2]), "=r"((r)[3]) : "r"(a))
#define LDSM2(r, a) \
    asm volatile("ldmatrix.sync.aligned.m8n8.x2.shared.b16 {%0,%1}, [%2];" \
        : "=r"((r)[0]), "=r"((r)[1]) : "r"(a))
#define MMA(c, a, bb) \
    asm volatile("mma.sync.aligned.m16n8k16.row.col.f32.f16.f16.f32 " \
        "{%0,%1,%2,%3}, {%4,%5,%6,%7}, {%8,%9}, {%0,%1,%2,%3};" \
        : "+f"((c)[0]), "+f"((c)[1]), "+f"((c)[2]), "+f"((c)[3]) \
        : "r"((a)[0]), "r"((a)[1]), "r"((a)[2]), "r"((a)[3]), "r"((bb)[0]), "r"((bb)[1]))

// ---------- 1) x -> [b][cb][p][ci16] fp16  +  pool partials ----------
__global__ __launch_bounds__(256) void xt_f16_kernel(const float* __restrict__ x,
        __half* __restrict__ X, float* __restrict__ ppart) {
    __shared__ float t[32][33];
    int b = blockIdx.z, p0 = blockIdx.x * 32, c0 = blockIdx.y * 32;
    int tx = threadIdx.x, ty = threadIdx.y;
    int tid = ty * 32 + tx;
#pragma unroll
    for (int i = 0; i < 4; i++)
        t[ty + 8 * i][tx] = x[((size_t)b * C_IN + c0 + ty + 8 * i) * HW + p0 + tx];
    __syncthreads();

    // pool partials: warp ty reduces channels ty*4 .. ty*4+3 over this 32-px tile
#pragma unroll
    for (int j = 0; j < 4; j++) {
        int cl = ty * 4 + j;
        float s = t[cl][tx];
#pragma unroll
        for (int o = 16; o; o >>= 1) s += __shfl_xor_sync(~0u, s, o);
        if (tx == 0)
            ppart[((size_t)(b * C_IN + c0 + cl) << 7) | (p0 >> 5)] = s;
    }

#pragma unroll
    for (int i = 0; i < 2; i++) {
        int idx = tid + 256 * i;
        int sub  = idx & 7;
        int pxcb = idx >> 3;
        int pxl  = pxcb & 31;
        int cbl  = pxcb >> 5;
        int cl   = cbl * 16 + sub * 2;
        int c    = c0 + cl;
        __half2 v = __floats2half2_rn(t[cl][pxl], t[cl + 1][pxl]);
        size_t o = ((((size_t)b * 8 + (c >> 4)) * HW + p0 + pxl) * 16 + (c & 15)) >> 1;
        ((__half2*)X)[o] = v;
    }
}

// ---------- 2) attention (pool-free, coalesced MLP) ----------
__global__ __launch_bounds__(512) void attn_kernel(const float* __restrict__ ppart,
        const float* __restrict__ prompt,
        const float* __restrict__ w1, const float* __restrict__ b1, const float* __restrict__ w2,
        const float* __restrict__ b2, const float* __restrict__ kbias,
        float* __restrict__ alphas, float* __restrict__ aggb) {
    int b = blockIdx.x, t = threadIdx.x;
    int wr = t >> 5, ln = t & 31;
    __shared__ float sp[C_IN], sh[HID], ss[HID], sc[K_], sal[K_];

    // finish pool: warp wr -> channels wr*8 .. wr*8+7; 128 partials each
#pragma unroll
    for (int j = 0; j < 8; j++) {
        int c = wr * 8 + j;
        const float* pp = ppart + ((size_t)(b * C_IN + c) << 7);
        float s = pp[ln] + pp[ln + 32] + pp[ln + 64] + pp[ln + 96];
#pragma unroll
        for (int o = 16; o; o >>= 1) s += __shfl_xor_sync(~0u, s, o);
        if (ln == 0) sp[c] = s * (1.f / (float)HW);
    }
    __syncthreads();

    {   // h = relu(W1 @ pooled + b1)
        const float4* sp4 = (const float4*)sp;
        float4 pv = sp4[ln];
#pragma unroll 4
        for (int jj = 0; jj < 32; jj++) {
            int j = wr * 32 + jj;
            float4 wv = ((const float4*)(w1 + (size_t)j * C_IN))[ln];
            float a = wv.x * pv.x + wv.y * pv.y + wv.z * pv.z + wv.w * pv.w;
#pragma unroll
            for (int o = 16; o; o >>= 1) a += __shfl_xor_sync(~0u, a, o);
            if (ln == 0) sh[j] = fmaxf(a + b1[j], 0.f);
        }
    }
    __syncthreads();
    {   // s = W2 @ h + b2
        const float4* sh4 = (const float4*)sh;
        float4 hv[4];
#pragma unroll
        for (int q = 0; q < 4; q++) hv[q] = sh4[ln + 32 * q];
#pragma unroll 2
        for (int jj = 0; jj < 32; jj++) {
            int j = wr * 32 + jj;
            const float4* row = (const float4*)(w2 + (size_t)j * HID);
            float a = 0.f;
#pragma unroll
            for (int q = 0; q < 4; q++) {
                float4 wv = row[ln + 32 * q];
                a = fmaf(wv.x, hv[q].x, a);
                a = fmaf(wv.y, hv[q].y, a);
                a = fmaf(wv.z, hv[q].z, a);
                a = fmaf(wv.w, hv[q].w, a);
            }
#pragma unroll
            for (int o = 16; o; o >>= 1) a += __shfl_xor_sync(~0u, a, o);
            if (ln == 0) ss[j] = a + b2[j];
        }
    }
    __syncthreads();

    if (wr < K_) {
        const float* pr = prompt + (size_t)wr * HID;
        float a = 0.f;
        for (int i = ln; i < HID; i += 32) a = fmaf(ss[i], pr[i], a);
#pragma unroll
        for (int o = 16; o; o >>= 1) a += __shfl_xor_sync(~0u, a, o);
        if (ln == 0) sc[wr] = a;
    }
    __syncthreads();
    if (t == 0) {
        float m = sc[0];
#pragma unroll
        for (int k = 1; k < K_; k++) m = fmaxf(m, sc[k]);
        float e[K_], su = 0.f;
#pragma unroll
        for (int k = 0; k < K_; k++) { e[k] = __expf(sc[k] - m); su += e[k]; }
        float inv = 1.f / su;
#pragma unroll
        for (int k = 0; k < K_; k++) { sal[k] = e[k] * inv; alphas[b * K_ + k] = sal[k]; }
    }
    __syncthreads();
    if (t < C_OUT) {
        float a = 0.f;
#pragma unroll
        for (int k = 0; k < K_; k++) a = fmaf(sal[k], kbias[k * C_OUT + t], a);
        aggb[b * C_OUT + t] = a;
    }
}

// ---------- 3) weight agg (+ counter reset) ----------
__global__ __launch_bounds__(128) void aggw_f16_kernel(const float* __restrict__ kw, const float* __restrict__ alphas,
        __half* __restrict__ A) {
    if (blockIdx.x == 0 && blockIdx.y == 0 && threadIdx.x == 0) g_ctr = 0;
    int oc = blockIdx.x, b = blockIdx.y, ci = threadIdx.x;
    __shared__ float skw[K_][C_IN * 9];
    __shared__ float a[K_];
    if (ci < K_) a[ci] = alphas[b * K_ + ci];
    for (int k = 0; k < K_; k++)
        for (int i = ci; i < C_IN * 9; i += 128)
            skw[k][i] = kw[(size_t)(k * C_OUT + oc) * (C_IN * 9) + i];
    __syncthreads();
    float acc[9];
#pragma unroll
    for (int t = 0; t < 9; t++) acc[t] = 0.f;
#pragma unroll
    for (int k = 0; k < K_; k++) {
        float al = a[k];
        const float* p = &skw[k][ci * 9];
#pragma unroll
        for (int t = 0; t < 9; t++) acc[t] = fmaf(al, p[t], acc[t]);
    }
#pragma unroll
    for (int t = 0; t < 9; t++) {
        size_t o = ((((size_t)(b * 9 + t) * 8 + (ci >> 4)) * C_OUT) + oc) * 16 + (ci & 15);
        A[o] = __float2half_rn(acc[t]);
    }
}

// ---------- 4) persistent HMMA conv (unchanged from R10/R11) ----------
#define PITCH 48
#define SM_A  0
#define SM_B  6144
#define BUF_SZ 12288
__global__ __launch_bounds__(256, 2) void conv_mma_kernel(
        const __half* __restrict__ aw, const __half* __restrict__ xt,
        const float* __restrict__ aggb, float* __restrict__ out)
{
    extern __shared__ __align__(128) char sm[];
    const uint32_t sbase = smem_u32(sm);
    __shared__ int s_nu[2];
    const int tid = threadIdx.x, wid = tid >> 5, lane = tid & 31;
    const int warp_m = wid & 3, warp_n = wid >> 2;

    const int row  = tid >> 1, half = tid & 1;
    const uint32_t aDst = sbase + SM_A + row * PITCH + half * 16;
    const uint32_t bDst = sbase + SM_B + row * PITCH + half * 16;
    const uint32_t offA = (uint32_t)((warp_m * 32 + (lane & 15)) * PITCH + (lane >> 4) * 16);
    const uint32_t offB = (uint32_t)((warp_n * 64 + (lane & 7)) * PITCH + ((lane >> 3) & 1) * 16);

    if (tid == 0) s_nu[0] = atomicAdd(&g_ctr, 1);
    __syncthreads();
    int c_u = s_nu[0];
    if (tid == 0) s_nu[1] = atomicAdd(&g_ctr, 1);
    int nslot = 1;

    int l_u = c_u, l_s = 0, l_buf = 0;

    float C[8][2][4];
#pragma unroll
    for (int i = 0; i < 8; i++)
#pragma unroll
        for (int j = 0; j < 2; j++)
#pragma unroll
            for (int q = 0; q < 4; q++) C[i][j][q] = 0.f;

#define ISSUE() do { \
    if (l_u < NUNITS) { \
        int b_ = l_u >> 5, y0_ = (l_u & 31) * 2; \
        int tap_ = l_s >> 3, cb_ = l_s & 7; \
        int yy_ = y0_ + (row >> 6) + tap_ / 3 - 1; \
        int xx_ = (row & 63) + tap_ % 3 - 1; \
        bool v_ = ((unsigned)yy_ < 64u) && ((unsigned)xx_ < 64u); \
        size_t boff_ = (size_t)b_ * 1048576 + (size_t)cb_ * 131072 \
                     + (v_ ? (size_t)(yy_ * 64 + xx_) * 32 : 0) + half * 16; \
        unsigned bsz_ = v_ ? 16u : 0u; \
        uint32_t bs_ = l_buf * BUF_SZ; \
        CPA(aDst + bs_, (const char*)aw + (size_t)b_ * 294912 + l_s * 4096 + row * 32 + half * 16, 16u); \
        CPA(bDst + bs_, (const char*)xt + boff_, bsz_); \
    } \
    l_s++; l_buf = (l_buf + 1) & 3; \
} while (0)

    ISSUE(); CP_COMMIT();
    ISSUE(); CP_COMMIT();
    ISSUE(); CP_COMMIT();

    uint32_t fA0[2][4], fB0[8][2], fA1[2][4], fB1[8][2];

    CP_WAIT2();
    __syncthreads();
    {
        const uint32_t bb = sbase;
        LDSM4(fA0[0], bb + SM_A + offA);
        LDSM4(fA0[1], bb + SM_A + offA + 16 * PITCH);
#pragma unroll
        for (int nt = 0; nt < 8; nt++) LDSM2(fB0[nt], bb + SM_B + offB + nt * 8 * PITCH);
    }
    int c_buf = 1;

#define STEP(CA, CB, NA, NB) do { \
    CP_WAIT1(); \
    __syncthreads(); \
    if (l_s == 72) { l_u = s_nu[nslot]; l_s = 0; } \
    ISSUE(); \
    CP_COMMIT(); \
    const uint32_t bbN = sbase + c_buf * BUF_SZ; \
    c_buf = (c_buf + 1) & 3; \
    LDSM4(NA[0], bbN + SM_A + offA); \
    LDSM4(NA[1], bbN + SM_A + offA + 16 * PITCH); \
    _Pragma("unroll") \
    for (int nt = 0; nt < 8; nt++) LDSM2(NB[nt], bbN + SM_B + offB + nt * 8 * PITCH); \
    _Pragma("unroll") \
    for (int nt = 0; nt < 8; nt++) { \
        MMA(C[nt][0], CA[0], CB[nt]); \
        MMA(C[nt][1], CA[1], CB[nt]); \
    } \
} while (0)

    while (c_u < NUNITS) {
        for (int c_s = 0; c_s < 72; c_s += 2) {
            STEP(fA0, fB0, fA1, fB1);
            STEP(fA1, fB1, fA0, fB0);
        }
        {
            int b_ = c_u >> 5, y_ = (c_u & 31) * 2 + warp_n;
            float* orow = out + (size_t)b_ * 128 * HW + y_ * 64;
#pragma unroll
            for (int mt = 0; mt < 2; mt++) {
                int oc0 = warp_m * 32 + mt * 16 + (lane >> 2);
                float bi0 = aggb[b_ * 128 + oc0];
                float bi1 = aggb[b_ * 128 + oc0 + 8];
#pragma unroll
                for (int nt = 0; nt < 8; nt++) {
                    int xcol = nt * 8 + 2 * (lane & 3);
                    float2 w0 = { C[nt][mt][0] + bi0, C[nt][mt][1] + bi0 };
                    float2 w1v = { C[nt][mt][2] + bi1, C[nt][mt][3] + bi1 };
                    *(float2*)(orow + (size_t)oc0 * HW + xcol) = w0;
                    *(float2*)(orow + (size_t)(oc0 + 8) * HW + xcol) = w1v;
                }
            }
        }
#pragma unroll
        for (int i = 0; i < 8; i++)
#pragma unroll
            for (int j = 0; j < 2; j++)
#pragma unroll
                for (int q = 0; q < 4; q++) C[i][j][q] = 0.f;

        c_u = s_nu[nslot];
        nslot ^= 1;
        if (tid == 0) s_nu[nslot] = atomicAdd(&g_ctr, 1);
    }
}

// ---------- host ----------
extern "C" void kernel_launch(void* const* d_in, const int* in_sizes, int n_in,
                              void* d_out, int out_size) {
    const float* x      = (const float*)d_in[0];
    const float* prompt = (const float*)d_in[1];
    const float* w1     = (const float*)d_in[2];
    const float* b1     = (const float*)d_in[3];
    const float* w2     = (const float*)d_in[4];
    const float* b2     = (const float*)d_in[5];
    const float* kw     = (const float*)d_in[6];
    const float* kbias  = (const float*)d_in[7];
    float* out = (float*)d_out;

    float *ppart, *alphas, *aggb;
    __half *xh, *awp;
    cudaGetSymbolAddress((void**)&ppart,  g_ppart);
    cudaGetSymbolAddress((void**)&alphas, g_alphas);
    cudaGetSymbolAddress((void**)&aggb,   g_aggb);
    cudaGetSymbolAddress((void**)&xh,     g_xt);
    cudaGetSymbolAddress((void**)&awp,    g_aw);

    cudaFuncSetAttribute(conv_mma_kernel, cudaFuncAttributeMaxDynamicSharedMemorySize, 4 * BUF_SZ);

    xt_f16_kernel<<<dim3(HW / 32, C_IN / 32, B_), dim3(32, 8)>>>(x, xh, ppart);
    attn_kernel<<<B_, 512>>>(ppart, prompt, w1, b1, w2, b2, kbias, alphas, aggb);
    aggw_f16_kernel<<<dim3(C_OUT, B_), 128>>>(kw, alphas, awp);
    conv_mma_kernel<<<GRID_P, 256, 4 * BUF_SZ>>>(awp, xh, aggb, out);
}

// round 13
// speedup vs baseline: 1.9199x; 1.0270x over previous
#include <cuda_runtime.h>
#include <cuda_fp16.h>
#include <stdint.h>

#define B_    32
#define C_IN  128
#define H_    64
#define W_    64
#define K_    8
#define C_OUT 128
#define HID   512
#define HW    4096
#define NUNITS 1024
#define GRID_P 296

__device__ float g_ppart[(size_t)B_ * C_IN * 128];
__device__ float g_alphas[B_ * K_];
__device__ float g_aggb[B_ * C_OUT];
__device__ int   g_ctr;
__device__ __half g_xt[(size_t)B_ * HW * C_IN];        // [b][cb][p][ci16]
__device__ __half g_aw[(size_t)B_ * 9 * C_OUT * C_IN]; // [b][tap][cb][oc][ci16]

__device__ __forceinline__ uint32_t smem_u32(const void* p) {
    uint32_t a;
    asm("{ .reg .u64 t; cvta.to.shared.u64 t, %1; cvt.u32.u64 %0, t; }" : "=r"(a) : "l"(p));
    return a;
}
#define CPA(dst, src, sz) \
    asm volatile("cp.async.cg.shared.global [%0], [%1], 16, %2;" :: "r"(dst), "l"(src), "r"(sz) : "memory")
#define CP_COMMIT() asm volatile("cp.async.commit_group;" ::: "memory")
#define CP_WAIT1()  asm volatile("cp.async.wait_group 1;" ::: "memory")
#define CP_WAIT2()  asm volatile("cp.async.wait_group 2;" ::: "memory")
#define LDSM4(r, a) \
    asm volatile("ldmatrix.sync.aligned.m8n8.x4.shared.b16 {%0,%1,%2,%3}, [%4];" \
        : "=r"((r)[0]), "=r"((r)[1]), "=r"((r)[2]), "=r"((r)[3]) : "r"(a))
#define LDSM2(r, a) \
    asm volatile("ldmatrix.sync.aligned.m8n8.x2.shared.b16 {%0,%1}, [%2];" \
        : "=r"((r)[0]), "=r"((r)[1]) : "r"(a))
#define MMA(c, a, bb) \
    asm volatile("mma.sync.aligned.m16n8k16.row.col.f32.f16.f16.f32 " \
        "{%0,%1,%2,%3}, {%4,%5,%6,%7}, {%8,%9}, {%0,%1,%2,%3};" \
        : "+f"((c)[0]), "+f"((c)[1]), "+f"((c)[2]), "+f"((c)[3]) \
        : "r"((a)[0]), "r"((a)[1]), "r"((a)[2]), "r"((a)[3]), "r"((bb)[0]), "r"((bb)[1]))

// ---------- 1) x -> [b][cb][p][ci16] fp16  +  pool partials ----------
__global__ __launch_bounds__(256) void xt_f16_kernel(const float* __restrict__ x,
        __half* __restrict__ X, float* __restrict__ ppart) {
    __shared__ float t[32][33];
    int b = blockIdx.z, p0 = blockIdx.x * 32, c0 = blockIdx.y * 32;
    int tx = threadIdx.x, ty = threadIdx.y;
    int tid = ty * 32 + tx;
#pragma unroll
    for (int i = 0; i < 4; i++)
        t[ty + 8 * i][tx] = x[((size_t)b * C_IN + c0 + ty + 8 * i) * HW + p0 + tx];
    __syncthreads();

#pragma unroll
    for (int j = 0; j < 4; j++) {
        int cl = ty * 4 + j;
        float s = t[cl][tx];
#pragma unroll
        for (int o = 16; o; o >>= 1) s += __shfl_xor_sync(~0u, s, o);
        if (tx == 0)
            ppart[((size_t)(b * C_IN + c0 + cl) << 7) | (p0 >> 5)] = s;
    }

#pragma unroll
    for (int i = 0; i < 2; i++) {
        int idx = tid + 256 * i;
        int sub  = idx & 7;
        int pxcb = idx >> 3;
        int pxl  = pxcb & 31;
        int cbl  = pxcb >> 5;
        int cl   = cbl * 16 + sub * 2;
        int c    = c0 + cl;
        __half2 v = __floats2half2_rn(t[cl][pxl], t[cl + 1][pxl]);
        size_t o = ((((size_t)b * 8 + (c >> 4)) * HW + p0 + pxl) * 16 + (c & 15)) >> 1;
        ((__half2*)X)[o] = v;
    }
}

// ---------- 2) attention (pool-free, coalesced MLP; resets g_ctr) ----------
__global__ __launch_bounds__(512) void attn_kernel(const float* __restrict__ ppart,
        const float* __restrict__ prompt,
        const float* __restrict__ w1, const float* __restrict__ b1, const float* __restrict__ w2,
        const float* __restrict__ b2, const float* __restrict__ kbias,
        float* __restrict__ alphas, float* __restrict__ aggb) {
    int b = blockIdx.x, t = threadIdx.x;
    int wr = t >> 5, ln = t & 31;
    if (b == 0 && t == 0) g_ctr = 0;
    __shared__ float sp[C_IN], sh[HID], ss[HID], sc[K_], sal[K_];

#pragma unroll
    for (int j = 0; j < 8; j++) {
        int c = wr * 8 + j;
        const float* pp = ppart + ((size_t)(b * C_IN + c) << 7);
        float s = pp[ln] + pp[ln + 32] + pp[ln + 64] + pp[ln + 96];
#pragma unroll
        for (int o = 16; o; o >>= 1) s += __shfl_xor_sync(~0u, s, o);
        if (ln == 0) sp[c] = s * (1.f / (float)HW);
    }
    __syncthreads();

    {   // h = relu(W1 @ pooled + b1)
        const float4* sp4 = (const float4*)sp;
        float4 pv = sp4[ln];
#pragma unroll 4
        for (int jj = 0; jj < 32; jj++) {
            int j = wr * 32 + jj;
            float4 wv = ((const float4*)(w1 + (size_t)j * C_IN))[ln];
            float a = wv.x * pv.x + wv.y * pv.y + wv.z * pv.z + wv.w * pv.w;
#pragma unroll
            for (int o = 16; o; o >>= 1) a += __shfl_xor_sync(~0u, a, o);
            if (ln == 0) sh[j] = fmaxf(a + b1[j], 0.f);
        }
    }
    __syncthreads();
    {   // s = W2 @ h + b2
        const float4* sh4 = (const float4*)sh;
        float4 hv[4];
#pragma unroll
        for (int q = 0; q < 4; q++) hv[q] = sh4[ln + 32 * q];
#pragma unroll 2
        for (int jj = 0; jj < 32; jj++) {
            int j = wr * 32 + jj;
            const float4* row = (const float4*)(w2 + (size_t)j * HID);
            float a = 0.f;
#pragma unroll
            for (int q = 0; q < 4; q++) {
                float4 wv = row[ln + 32 * q];
                a = fmaf(wv.x, hv[q].x, a);
                a = fmaf(wv.y, hv[q].y, a);
                a = fmaf(wv.z, hv[q].z, a);
                a = fmaf(wv.w, hv[q].w, a);
            }
#pragma unroll
            for (int o = 16; o; o >>= 1) a += __shfl_xor_sync(~0u, a, o);
            if (ln == 0) ss[j] = a + b2[j];
        }
    }
    __syncthreads();

    if (wr < K_) {
        const float* pr = prompt + (size_t)wr * HID;
        float a = 0.f;
        for (int i = ln; i < HID; i += 32) a = fmaf(ss[i], pr[i], a);
#pragma unroll
        for (int o = 16; o; o >>= 1) a += __shfl_xor_sync(~0u, a, o);
        if (ln == 0) sc[wr] = a;
    }
    __syncthreads();
    if (t == 0) {
        float m = sc[0];
#pragma unroll
        for (int k = 1; k < K_; k++) m = fmaxf(m, sc[k]);
        float e[K_], su = 0.f;
#pragma unroll
        for (int k = 0; k < K_; k++) { e[k] = __expf(sc[k] - m); su += e[k]; }
        float inv = 1.f / su;
#pragma unroll
        for (int k = 0; k < K_; k++) { sal[k] = e[k] * inv; alphas[b * K_ + k] = sal[k]; }
    }
    __syncthreads();
    if (t < C_OUT) {
        float a = 0.f;
#pragma unroll
        for (int k = 0; k < K_; k++) a = fmaf(sal[k], kbias[k * C_OUT + t], a);
        aggb[b * C_OUT + t] = a;
    }
}

// ---------- 3) weight agg: one block per oc, kw slice staged ONCE ----------
__global__ __launch_bounds__(256) void aggw_f16_kernel(const float* __restrict__ kw,
        const float* __restrict__ alphas, __half* __restrict__ A) {
    const int oc = blockIdx.x, tid = threadIdx.x;
    __shared__ float skw[K_][C_IN * 9];     // 36 KB
    __shared__ float sal[B_ * K_];          // 256 alphas
    sal[tid] = alphas[tid];
#pragma unroll
    for (int k = 0; k < K_; k++)
        for (int i = tid; i < C_IN * 9; i += 256)
            skw[k][i] = kw[(size_t)(k * C_OUT + oc) * (C_IN * 9) + i];
    __syncthreads();

    const int bh = tid >> 7;               // half: b 0-15 or 16-31
    const int ci = tid & 127;
    const float* p0 = &skw[0][ci * 9];
#pragma unroll 2
    for (int b = bh * 16; b < bh * 16 + 16; b++) {
        float acc[9];
#pragma unroll
        for (int t = 0; t < 9; t++) acc[t] = 0.f;
#pragma unroll
        for (int k = 0; k < K_; k++) {
            float al = sal[b * K_ + k];
            const float* p = p0 + k * (C_IN * 9);
#pragma unroll
            for (int t = 0; t < 9; t++) acc[t] = fmaf(al, p[t], acc[t]);
        }
#pragma unroll
        for (int t = 0; t < 9; t++) {
            size_t o = ((((size_t)(b * 9 + t) * 8 + (ci >> 4)) * C_OUT) + oc) * 16 + (ci & 15);
            A[o] = __float2half_rn(acc[t]);
        }
    }
}

// ---------- 4) persistent HMMA conv (unchanged) ----------
#define PITCH 48
#define SM_A  0
#define SM_B  6144
#define BUF_SZ 12288
__global__ __launch_bounds__(256, 2) void conv_mma_kernel(
        const __half* __restrict__ aw, const __half* __restrict__ xt,
        const float* __restrict__ aggb, float* __restrict__ out)
{
    extern __shared__ __align__(128) char sm[];
    const uint32_t sbase = smem_u32(sm);
    __shared__ int s_nu[2];
    const int tid = threadIdx.x, wid = tid >> 5, lane = tid & 31;
    const int warp_m = wid & 3, warp_n = wid >> 2;

    const int row  = tid >> 1, half = tid & 1;
    const uint32_t aDst = sbase + SM_A + row * PITCH + half * 16;
    const uint32_t bDst = sbase + SM_B + row * PITCH + half * 16;
    const uint32_t offA = (uint32_t)((warp_m * 32 + (lane & 15)) * PITCH + (lane >> 4) * 16);
    const uint32_t offB = (uint32_t)((warp_n * 64 + (lane & 7)) * PITCH + ((lane >> 3) & 1) * 16);

    if (tid == 0) s_nu[0] = atomicAdd(&g_ctr, 1);
    __syncthreads();
    int c_u = s_nu[0];
    if (tid == 0) s_nu[1] = atomicAdd(&g_ctr, 1);
    int nslot = 1;

    int l_u = c_u, l_s = 0, l_buf = 0;

    float C[8][2][4];
#pragma unroll
    for (int i = 0; i < 8; i++)
#pragma unroll
        for (int j = 0; j < 2; j++)
#pragma unroll
            for (int q = 0; q < 4; q++) C[i][j][q] = 0.f;

#define ISSUE() do { \
    if (l_u < NUNITS) { \
        int b_ = l_u >> 5, y0_ = (l_u & 31) * 2; \
        int tap_ = l_s >> 3, cb_ = l_s & 7; \
        int yy_ = y0_ + (row >> 6) + tap_ / 3 - 1; \
        int xx_ = (row & 63) + tap_ % 3 - 1; \
        bool v_ = ((unsigned)yy_ < 64u) && ((unsigned)xx_ < 64u); \
        size_t boff_ = (size_t)b_ * 1048576 + (size_t)cb_ * 131072 \
                     + (v_ ? (size_t)(yy_ * 64 + xx_) * 32 : 0) + half * 16; \
        unsigned bsz_ = v_ ? 16u : 0u; \
        uint32_t bs_ = l_buf * BUF_SZ; \
        CPA(aDst + bs_, (const char*)aw + (size_t)b_ * 294912 + l_s * 4096 + row * 32 + half * 16, 16u); \
        CPA(bDst + bs_, (const char*)xt + boff_, bsz_); \
    } \
    l_s++; l_buf = (l_buf + 1) & 3; \
} while (0)

    ISSUE(); CP_COMMIT();
    ISSUE(); CP_COMMIT();
    ISSUE(); CP_COMMIT();

    uint32_t fA0[2][4], fB0[8][2], fA1[2][4], fB1[8][2];

    CP_WAIT2();
    __syncthreads();
    {
        const uint32_t bb = sbase;
        LDSM4(fA0[0], bb + SM_A + offA);
        LDSM4(fA0[1], bb + SM_A + offA + 16 * PITCH);
#pragma unroll
        for (int nt = 0; nt < 8; nt++) LDSM2(fB0[nt], bb + SM_B + offB + nt * 8 * PITCH);
    }
    int c_buf = 1;

#define STEP(CA, CB, NA, NB) do { \
    CP_WAIT1(); \
    __syncthreads(); \
    if (l_s == 72) { l_u = s_nu[nslot]; l_s = 0; } \
    ISSUE(); \
    CP_COMMIT(); \
    const uint32_t bbN = sbase + c_buf * BUF_SZ; \
    c_buf = (c_buf + 1) & 3; \
    LDSM4(NA[0], bbN + SM_A + offA); \
    LDSM4(NA[1], bbN + SM_A + offA + 16 * PITCH); \
    _Pragma("unroll") \
    for (int nt = 0; nt < 8; nt++) LDSM2(NB[nt], bbN + SM_B + offB + nt * 8 * PITCH); \
    _Pragma("unroll") \
    for (int nt = 0; nt < 8; nt++) { \
        MMA(C[nt][0], CA[0], CB[nt]); \
        MMA(C[nt][1], CA[1], CB[nt]); \
    } \
} while (0)

    while (c_u < NUNITS) {
        for (int c_s = 0; c_s < 72; c_s += 2) {
            STEP(fA0, fB0, fA1, fB1);
            STEP(fA1, fB1, fA0, fB0);
        }
        {
            int b_ = c_u >> 5, y_ = (c_u & 31) * 2 + warp_n;
            float* orow = out + (size_t)b_ * 128 * HW + y_ * 64;
#pragma unroll
            for (int mt = 0; mt < 2; mt++) {
                int oc0 = warp_m * 32 + mt * 16 + (lane >> 2);
                float bi0 = aggb[b_ * 128 + oc0];
                float bi1 = aggb[b_ * 128 + oc0 + 8];
#pragma unroll
                for (int nt = 0; nt < 8; nt++) {
                    int xcol = nt * 8 + 2 * (lane & 3);
                    float2 w0 = { C[nt][mt][0] + bi0, C[nt][mt][1] + bi0 };
                    float2 w1v = { C[nt][mt][2] + bi1, C[nt][mt][3] + bi1 };
                    *(float2*)(orow + (size_t)oc0 * HW + xcol) = w0;
                    *(float2*)(orow + (size_t)(oc0 + 8) * HW + xcol) = w1v;
                }
            }
        }
#pragma unroll
        for (int i = 0; i < 8; i++)
#pragma unroll
            for (int j = 0; j < 2; j++)
#pragma unroll
                for (int q = 0; q < 4; q++) C[i][j][q] = 0.f;

        c_u = s_nu[nslot];
        nslot ^= 1;
        if (tid == 0) s_nu[nslot] = atomicAdd(&g_ctr, 1);
    }
}

// ---------- host ----------
extern "C" void kernel_launch(void* const* d_in, const int* in_sizes, int n_in,
                              void* d_out, int out_size) {
    const float* x      = (const float*)d_in[0];
    const float* prompt = (const float*)d_in[1];
    const float* w1     = (const float*)d_in[2];
    const float* b1     = (const float*)d_in[3];
    const float* w2     = (const float*)d_in[4];
    const float* b2     = (const float*)d_in[5];
    const float* kw     = (const float*)d_in[6];
    const float* kbias  = (const float*)d_in[7];
    float* out = (float*)d_out;

    float *ppart, *alphas, *aggb;
    __half *xh, *awp;
    cudaGetSymbolAddress((void**)&ppart,  g_ppart);
    cudaGetSymbolAddress((void**)&alphas, g_alphas);
    cudaGetSymbolAddress((void**)&aggb,   g_aggb);
    cudaGetSymbolAddress((void**)&xh,     g_xt);
    cudaGetSymbolAddress((void**)&awp,    g_aw);

    cudaFuncSetAttribute(conv_mma_kernel, cudaFuncAttributeMaxDynamicSharedMemorySize, 4 * BUF_SZ);

    xt_f16_kernel<<<dim3(HW / 32, C_IN / 32, B_), dim3(32, 8)>>>(x, xh, ppart);
    attn_kernel<<<B_, 512>>>(ppart, prompt, w1, b1, w2, b2, kbias, alphas, aggb);
    aggw_f16_kernel<<<C_OUT, 256>>>(kw, alphas, awp);
    conv_mma_kernel<<<GRID_P, 256, 4 * BUF_SZ>>>(awp, xh, aggb, out);
}

// round 14
// speedup vs baseline: 1.9907x; 1.0369x over previous
#include <cuda_runtime.h>
#include <cuda_fp16.h>
#include <stdint.h>

#define B_    32
#define C_IN  128
#define H_    64
#define W_    64
#define K_    8
#define C_OUT 128
#define HID   512
#define HW    4096
#define NUNITS 1024
#define GRID_P 296

__device__ float g_ppart[(size_t)B_ * C_IN * 32];      // [b][c][pblk128]
__device__ float g_alphas[B_ * K_];
__device__ float g_aggb[B_ * C_OUT];
__device__ int   g_ctr;
__device__ __half g_xt[(size_t)B_ * HW * C_IN];        // [b][cb][p][ci16]
__device__ __half g_aw[(size_t)B_ * 9 * C_OUT * C_IN]; // [b][tap][cb][oc][ci16]

__device__ __forceinline__ uint32_t smem_u32(const void* p) {
    uint32_t a;
    asm("{ .reg .u64 t; cvta.to.shared.u64 t, %1; cvt.u32.u64 %0, t; }" : "=r"(a) : "l"(p));
    return a;
}
#define CPA(dst, src, sz) \
    asm volatile("cp.async.cg.shared.global [%0], [%1], 16, %2;" :: "r"(dst), "l"(src), "r"(sz) : "memory")
#define CP_COMMIT() asm volatile("cp.async.commit_group;" ::: "memory")
#define CP_WAIT1()  asm volatile("cp.async.wait_group 1;" ::: "memory")
#define CP_WAIT2()  asm volatile("cp.async.wait_group 2;" ::: "memory")
#define LDSM4(r, a) \
    asm volatile("ldmatrix.sync.aligned.m8n8.x4.shared.b16 {%0,%1,%2,%3}, [%4];" \
        : "=r"((r)[0]), "=r"((r)[1]), "=r"((r)[2]), "=r"((r)[3]) : "r"(a))
#define LDSM2(r, a) \
    asm volatile("ldmatrix.sync.aligned.m8n8.x2.shared.b16 {%0,%1}, [%2];" \
        : "=r"((r)[0]), "=r"((r)[1]) : "r"(a))
#define MMA(c, a, bb) \
    asm volatile("mma.sync.aligned.m16n8k16.row.col.f32.f16.f16.f32 " \
        "{%0,%1,%2,%3}, {%4,%5,%6,%7}, {%8,%9}, {%0,%1,%2,%3};" \
        : "+f"((c)[0]), "+f"((c)[1]), "+f"((c)[2]), "+f"((c)[3]) \
        : "r"((a)[0]), "r"((a)[1]), "r"((a)[2]), "r"((a)[3]), "r"((bb)[0]), "r"((bb)[1]))

// ---------- 1) x -> [b][cb][p][ci16] fp16  +  pool partials (vectorized) ----------
#define XPITCH 136
__global__ __launch_bounds__(256) void xt_f16_kernel(const float* __restrict__ x,
        __half* __restrict__ X, float* __restrict__ ppart) {
    __shared__ float t[32 * XPITCH];       // 17,408 B
    const int b = blockIdx.z, p0 = blockIdx.x * 128, c0 = blockIdx.y * 32;
    const int tid = threadIdx.x;

    // load 32ch x 128px as float4 (1024 f4, 4 per thread), coalesced
#pragma unroll
    for (int i = 0; i < 4; i++) {
        int idx = tid + 256 * i;           // 0..1023
        int c  = idx >> 5;                 // 0..31
        int f4 = idx & 31;                 // 0..31
        float4 v = ((const float4*)(x + ((size_t)b * C_IN + c0 + c) * HW + p0))[f4];
        *(float4*)&t[c * XPITCH + f4 * 4] = v;
    }
    __syncthreads();

    // pool partials: warp w reduces channels w*4..w*4+3 over 128 px
    {
        int w = tid >> 5, ln = tid & 31;
#pragma unroll
        for (int j = 0; j < 4; j++) {
            int c = w * 4 + j;
            const float* r = &t[c * XPITCH];
            float s = r[ln] + r[ln + 32] + r[ln + 64] + r[ln + 96];
#pragma unroll
            for (int o = 16; o; o >>= 1) s += __shfl_xor_sync(~0u, s, o);
            if (ln == 0)
                ppart[((size_t)(b * C_IN + c0 + c)) * 32 + (p0 >> 7)] = s;
        }
    }

    // write half2: 2048 outputs, 8 per thread, 128B-coalesced per warp
#pragma unroll
    for (int i = 0; i < 8; i++) {
        int idx  = tid + 256 * i;          // 0..2047
        int sub  = idx & 7;                // ci pair within 16
        int pxcb = idx >> 3;
        int pxl  = pxcb & 127;
        int cbl  = pxcb >> 7;              // 0..1
        int cl   = cbl * 16 + sub * 2;
        int c    = c0 + cl;
        __half2 v = __floats2half2_rn(t[cl * XPITCH + pxl], t[(cl + 1) * XPITCH + pxl]);
        size_t o = ((((size_t)b * 8 + (c >> 4)) * HW + p0 + pxl) * 16 + (c & 15)) >> 1;
        ((__half2*)X)[o] = v;
    }
}

// ---------- 2) attention (resets g_ctr) ----------
__global__ __launch_bounds__(512) void attn_kernel(const float* __restrict__ ppart,
        const float* __restrict__ prompt,
        const float* __restrict__ w1, const float* __restrict__ b1, const float* __restrict__ w2,
        const float* __restrict__ b2, const float* __restrict__ kbias,
        float* __restrict__ alphas, float* __restrict__ aggb) {
    int b = blockIdx.x, t = threadIdx.x;
    int wr = t >> 5, ln = t & 31;
    if (b == 0 && t == 0) g_ctr = 0;
    __shared__ float sp[C_IN], sh[HID], ss[HID], sc[K_], sal[K_];

    // finish pool: 32 partials per channel
#pragma unroll
    for (int j = 0; j < 8; j++) {
        int c = wr * 8 + j;
        float s = ppart[((size_t)(b * C_IN + c)) * 32 + ln];
#pragma unroll
        for (int o = 16; o; o >>= 1) s += __shfl_xor_sync(~0u, s, o);
        if (ln == 0) sp[c] = s * (1.f / (float)HW);
    }
    __syncthreads();

    {   // h = relu(W1 @ pooled + b1)
        const float4* sp4 = (const float4*)sp;
        float4 pv = sp4[ln];
#pragma unroll 4
        for (int jj = 0; jj < 32; jj++) {
            int j = wr * 32 + jj;
            float4 wv = ((const float4*)(w1 + (size_t)j * C_IN))[ln];
            float a = wv.x * pv.x + wv.y * pv.y + wv.z * pv.z + wv.w * pv.w;
#pragma unroll
            for (int o = 16; o; o >>= 1) a += __shfl_xor_sync(~0u, a, o);
            if (ln == 0) sh[j] = fmaxf(a + b1[j], 0.f);
        }
    }
    __syncthreads();
    {   // s = W2 @ h + b2
        const float4* sh4 = (const float4*)sh;
        float4 hv[4];
#pragma unroll
        for (int q = 0; q < 4; q++) hv[q] = sh4[ln + 32 * q];
#pragma unroll 2
        for (int jj = 0; jj < 32; jj++) {
            int j = wr * 32 + jj;
            const float4* row = (const float4*)(w2 + (size_t)j * HID);
            float a = 0.f;
#pragma unroll
            for (int q = 0; q < 4; q++) {
                float4 wv = row[ln + 32 * q];
                a = fmaf(wv.x, hv[q].x, a);
                a = fmaf(wv.y, hv[q].y, a);
                a = fmaf(wv.z, hv[q].z, a);
                a = fmaf(wv.w, hv[q].w, a);
            }
#pragma unroll
            for (int o = 16; o; o >>= 1) a += __shfl_xor_sync(~0u, a, o);
            if (ln == 0) ss[j] = a + b2[j];
        }
    }
    __syncthreads();

    if (wr < K_) {
        const float* pr = prompt + (size_t)wr * HID;
        float a = 0.f;
        for (int i = ln; i < HID; i += 32) a = fmaf(ss[i], pr[i], a);
#pragma unroll
        for (int o = 16; o; o >>= 1) a += __shfl_xor_sync(~0u, a, o);
        if (ln == 0) sc[wr] = a;
    }
    __syncthreads();
    if (t == 0) {
        float m = sc[0];
#pragma unroll
        for (int k = 1; k < K_; k++) m = fmaxf(m, sc[k]);
        float e[K_], su = 0.f;
#pragma unroll
        for (int k = 0; k < K_; k++) { e[k] = __expf(sc[k] - m); su += e[k]; }
        float inv = 1.f / su;
#pragma unroll
        for (int k = 0; k < K_; k++) { sal[k] = e[k] * inv; alphas[b * K_ + k] = sal[k]; }
    }
    __syncthreads();
    if (t < C_OUT) {
        float a = 0.f;
#pragma unroll
        for (int k = 0; k < K_; k++) a = fmaf(sal[k], kbias[k * C_OUT + t], a);
        aggb[b * C_OUT + t] = a;
    }
}

// ---------- 3) weight agg: one block per oc, kw slice staged once ----------
__global__ __launch_bounds__(256) void aggw_f16_kernel(const float* __restrict__ kw,
        const float* __restrict__ alphas, __half* __restrict__ A) {
    const int oc = blockIdx.x, tid = threadIdx.x;
    __shared__ float skw[K_][C_IN * 9];
    __shared__ float sal[B_ * K_];
    sal[tid] = alphas[tid];
#pragma unroll
    for (int k = 0; k < K_; k++)
        for (int i = tid; i < C_IN * 9; i += 256)
            skw[k][i] = kw[(size_t)(k * C_OUT + oc) * (C_IN * 9) + i];
    __syncthreads();

    const int bh = tid >> 7;
    const int ci = tid & 127;
    const float* p0 = &skw[0][ci * 9];
#pragma unroll 2
    for (int b = bh * 16; b < bh * 16 + 16; b++) {
        float acc[9];
#pragma unroll
        for (int t = 0; t < 9; t++) acc[t] = 0.f;
#pragma unroll
        for (int k = 0; k < K_; k++) {
            float al = sal[b * K_ + k];
            const float* p = p0 + k * (C_IN * 9);
#pragma unroll
            for (int t = 0; t < 9; t++) acc[t] = fmaf(al, p[t], acc[t]);
        }
#pragma unroll
        for (int t = 0; t < 9; t++) {
            size_t o = ((((size_t)(b * 9 + t) * 8 + (ci >> 4)) * C_OUT) + oc) * 16 + (ci & 15);
            A[o] = __float2half_rn(acc[t]);
        }
    }
}

// ---------- 4) persistent HMMA conv (unchanged) ----------
#define PITCH 48
#define SM_A  0
#define SM_B  6144
#define BUF_SZ 12288
__global__ __launch_bounds__(256, 2) void conv_mma_kernel(
        const __half* __restrict__ aw, const __half* __restrict__ xt,
        const float* __restrict__ aggb, float* __restrict__ out)
{
    extern __shared__ __align__(128) char sm[];
    const uint32_t sbase = smem_u32(sm);
    __shared__ int s_nu[2];
    const int tid = threadIdx.x, wid = tid >> 5, lane = tid & 31;
    const int warp_m = wid & 3, warp_n = wid >> 2;

    const int row  = tid >> 1, half = tid & 1;
    const uint32_t aDst = sbase + SM_A + row * PITCH + half * 16;
    const uint32_t bDst = sbase + SM_B + row * PITCH + half * 16;
    const uint32_t offA = (uint32_t)((warp_m * 32 + (lane & 15)) * PITCH + (lane >> 4) * 16);
    const uint32_t offB = (uint32_t)((warp_n * 64 + (lane & 7)) * PITCH + ((lane >> 3) & 1) * 16);

    if (tid == 0) s_nu[0] = atomicAdd(&g_ctr, 1);
    __syncthreads();
    int c_u = s_nu[0];
    if (tid == 0) s_nu[1] = atomicAdd(&g_ctr, 1);
    int nslot = 1;

    int l_u = c_u, l_s = 0, l_buf = 0;

    float C[8][2][4];
#pragma unroll
    for (int i = 0; i < 8; i++)
#pragma unroll
        for (int j = 0; j < 2; j++)
#pragma unroll
            for (int q = 0; q < 4; q++) C[i][j][q] = 0.f;

#define ISSUE() do { \
    if (l_u < NUNITS) { \
        int b_ = l_u >> 5, y0_ = (l_u & 31) * 2; \
        int tap_ = l_s >> 3, cb_ = l_s & 7; \
        int yy_ = y0_ + (row >> 6) + tap_ / 3 - 1; \
        int xx_ = (row & 63) + tap_ % 3 - 1; \
        bool v_ = ((unsigned)yy_ < 64u) && ((unsigned)xx_ < 64u); \
        size_t boff_ = (size_t)b_ * 1048576 + (size_t)cb_ * 131072 \
                     + (v_ ? (size_t)(yy_ * 64 + xx_) * 32 : 0) + half * 16; \
        unsigned bsz_ = v_ ? 16u : 0u; \
        uint32_t bs_ = l_buf * BUF_SZ; \
        CPA(aDst + bs_, (const char*)aw + (size_t)b_ * 294912 + l_s * 4096 + row * 32 + half * 16, 16u); \
        CPA(bDst + bs_, (const char*)xt + boff_, bsz_); \
    } \
    l_s++; l_buf = (l_buf + 1) & 3; \
} while (0)

    ISSUE(); CP_COMMIT();
    ISSUE(); CP_COMMIT();
    ISSUE(); CP_COMMIT();

    uint32_t fA0[2][4], fB0[8][2], fA1[2][4], fB1[8][2];

    CP_WAIT2();
    __syncthreads();
    {
        const uint32_t bb = sbase;
        LDSM4(fA0[0], bb + SM_A + offA);
        LDSM4(fA0[1], bb + SM_A + offA + 16 * PITCH);
#pragma unroll
        for (int nt = 0; nt < 8; nt++) LDSM2(fB0[nt], bb + SM_B + offB + nt * 8 * PITCH);
    }
    int c_buf = 1;

#define STEP(CA, CB, NA, NB) do { \
    CP_WAIT1(); \
    __syncthreads(); \
    if (l_s == 72) { l_u = s_nu[nslot]; l_s = 0; } \
    ISSUE(); \
    CP_COMMIT(); \
    const uint32_t bbN = sbase + c_buf * BUF_SZ; \
    c_buf = (c_buf + 1) & 3; \
    LDSM4(NA[0], bbN + SM_A + offA); \
    LDSM4(NA[1], bbN + SM_A + offA + 16 * PITCH); \
    _Pragma("unroll") \
    for (int nt = 0; nt < 8; nt++) LDSM2(NB[nt], bbN + SM_B + offB + nt * 8 * PITCH); \
    _Pragma("unroll") \
    for (int nt = 0; nt < 8; nt++) { \
        MMA(C[nt][0], CA[0], CB[nt]); \
        MMA(C[nt][1], CA[1], CB[nt]); \
    } \
} while (0)

    while (c_u < NUNITS) {
        for (int c_s = 0; c_s < 72; c_s += 2) {
            STEP(fA0, fB0, fA1, fB1);
            STEP(fA1, fB1, fA0, fB0);
        }
        {
            int b_ = c_u >> 5, y_ = (c_u & 31) * 2 + warp_n;
            float* orow = out + (size_t)b_ * 128 * HW + y_ * 64;
#pragma unroll
            for (int mt = 0; mt < 2; mt++) {
                int oc0 = warp_m * 32 + mt * 16 + (lane >> 2);
                float bi0 = aggb[b_ * 128 + oc0];
                float bi1 = aggb[b_ * 128 + oc0 + 8];
#pragma unroll
                for (int nt = 0; nt < 8; nt++) {
                    int xcol = nt * 8 + 2 * (lane & 3);
                    float2 w0 = { C[nt][mt][0] + bi0, C[nt][mt][1] + bi0 };
                    float2 w1v = { C[nt][mt][2] + bi1, C[nt][mt][3] + bi1 };
                    *(float2*)(orow + (size_t)oc0 * HW + xcol) = w0;
                    *(float2*)(orow + (size_t)(oc0 + 8) * HW + xcol) = w1v;
                }
            }
        }
#pragma unroll
        for (int i = 0; i < 8; i++)
#pragma unroll
            for (int j = 0; j < 2; j++)
#pragma unroll
                for (int q = 0; q < 4; q++) C[i][j][q] = 0.f;

        c_u = s_nu[nslot];
        nslot ^= 1;
        if (tid == 0) s_nu[nslot] = atomicAdd(&g_ctr, 1);
    }
}

// ---------- host ----------
extern "C" void kernel_launch(void* const* d_in, const int* in_sizes, int n_in,
                              void* d_out, int out_size) {
    const float* x      = (const float*)d_in[0];
    const float* prompt = (const float*)d_in[1];
    const float* w1     = (const float*)d_in[2];
    const float* b1     = (const float*)d_in[3];
    const float* w2     = (const float*)d_in[4];
    const float* b2     = (const float*)d_in[5];
    const float* kw     = (const float*)d_in[6];
    const float* kbias  = (const float*)d_in[7];
    float* out = (float*)d_out;

    float *ppart, *alphas, *aggb;
    __half *xh, *awp;
    cudaGetSymbolAddress((void**)&ppart,  g_ppart);
    cudaGetSymbolAddress((void**)&alphas, g_alphas);
    cudaGetSymbolAddress((void**)&aggb,   g_aggb);
    cudaGetSymbolAddress((void**)&xh,     g_xt);
    cudaGetSymbolAddress((void**)&awp,    g_aw);

    cudaFuncSetAttribute(conv_mma_kernel, cudaFuncAttributeMaxDynamicSharedMemorySize, 4 * BUF_SZ);

    xt_f16_kernel<<<dim3(HW / 128, C_IN / 32, B_), 256>>>(x, xh, ppart);
    attn_kernel<<<B_, 512>>>(ppart, prompt, w1, b1, w2, b2, kbias, alphas, aggb);
    aggw_f16_kernel<<<C_OUT, 256>>>(kw, alphas, awp);
    conv_mma_kernel<<<GRID_P, 256, 4 * BUF_SZ>>>(awp, xh, aggb, out);
}